// round 11
// baseline (speedup 1.0000x reference)
#include <cuda_runtime.h>

#define NSZ   1536
#define NNSZ  (NSZ * NSZ)          // 2,359,296  (== 1152*2048)

// ---------------------------------------------------------------------------
// Scratch (device globals -- allocation-free rule). 151 MB BSS.
// z planes SoA: g_z[c * NNSZ + p]; reused in place (widths 16->16->8->8,
// each thread reads all inputs at its position before writing the same one).
// ---------------------------------------------------------------------------
__device__ __align__(16) float  g_z[16 * NNSZ];
__device__ double g_sumP[8][16];     // sliced partials (8 copies spread atomics)
__device__ double g_sqP[8][16];
__device__ float  g_scaleA[4][16];   // BN affine: y = z*scale + shift
__device__ float  g_shiftA[4][16];

// ---- packed f32x2 helpers (sm_103a) ---------------------------------------
__device__ __forceinline__ unsigned long long f2fma(unsigned long long a,
                                                    unsigned long long b,
                                                    unsigned long long c) {
    unsigned long long d;
    asm("fma.rn.f32x2 %0, %1, %2, %3;" : "=l"(d) : "l"(a), "l"(b), "l"(c));
    return d;
}
__device__ __forceinline__ unsigned long long f2add(unsigned long long a,
                                                    unsigned long long b) {
    unsigned long long d;
    asm("add.rn.f32x2 %0, %1, %2;" : "=l"(d) : "l"(a), "l"(b));
    return d;
}
__device__ __forceinline__ unsigned long long f2dup(float x) {
    unsigned long long d;
    unsigned u = __float_as_uint(x);
    asm("mov.b64 %0, {%1, %1};" : "=l"(d) : "r"(u));
    return d;
}
__device__ __forceinline__ float f2lo(unsigned long long a) {
    return __uint_as_float((unsigned)(a & 0xFFFFFFFFull));
}
__device__ __forceinline__ float f2hi(unsigned long long a) {
    return __uint_as_float((unsigned)(a >> 32));
}

// ---------------------------------------------------------------------------
// K0: zero stats partials
// ---------------------------------------------------------------------------
__global__ void k_zero() {
    int t = threadIdx.x;
    if (t < 128) {
        ((double*)g_sumP)[t] = 0.0;
        ((double*)g_sqP)[t]  = 0.0;
    }
}

// ---------------------------------------------------------------------------
// K1: adj + layer-1 matmul + bias -> z1 (16 planes) + stats.
// (unchanged since R8 -- inferred ~115us; f32x2 packed math, 4 j-pos/thread)
// ---------------------------------------------------------------------------
__global__ void __launch_bounds__(256, 2) k_l1(const float* __restrict__ x,
                                               const float* __restrict__ W1,
                                               const float* __restrict__ b1) {
    __shared__ __align__(16) float sNXjT[64][132];  // 33.8KB, rows 528B
    __shared__ __align__(16) float sXi[8][64];      // 2KB
    __shared__ __align__(16) float sWd[64][32];     // 8KB dup'd weight pairs
    __shared__ float sB[16];
    __shared__ float sRed[8][32];

    const int t  = threadIdx.x;
    const int j0 = blockIdx.x * 128;
    const int i0 = blockIdx.y * 8;

    for (int idx = t; idx < 128 * 64; idx += 256) {
        int jj = idx >> 6, c = idx & 63;
        sNXjT[c][jj] = -x[(j0 + jj) * 64 + c];
    }
    for (int idx = t; idx < 8 * 64; idx += 256) {
        int r = idx >> 6, c = idx & 63;
        sXi[r][c] = x[(i0 + r) * 64 + c];
    }
    for (int idx = t; idx < 64 * 16; idx += 256) {
        int c = idx >> 4, o = idx & 15;
        float w = W1[o * 64 + c];
        sWd[c][2 * o]     = w;
        sWd[c][2 * o + 1] = w;
    }
    if (t < 16) sB[t] = b1[t];
    __syncthreads();

    const int jq   = t & 31;
    const int irow = t >> 5;

    unsigned long long acc0[16], acc1[16];
#pragma unroll
    for (int o = 0; o < 16; o++) { acc0[o] = 0ull; acc1[o] = 0ull; }

    const unsigned long long ABSM = 0x7FFFFFFF7FFFFFFFull;

#pragma unroll 8
    for (int c = 0; c < 64; c++) {
        unsigned long long xid = f2dup(sXi[irow][c]);
        ulonglong2 nx = *(const ulonglong2*)&sNXjT[c][4 * jq];
        unsigned long long d0 = f2add(xid, nx.x) & ABSM;
        unsigned long long d1 = f2add(xid, nx.y) & ABSM;
        const ulonglong2* wrow = (const ulonglong2*)&sWd[c][0];
#pragma unroll
        for (int o2 = 0; o2 < 8; o2++) {
            ulonglong2 wp = wrow[o2];
            acc0[2 * o2]     = f2fma(d0, wp.x, acc0[2 * o2]);
            acc1[2 * o2]     = f2fma(d1, wp.x, acc1[2 * o2]);
            acc0[2 * o2 + 1] = f2fma(d0, wp.y, acc0[2 * o2 + 1]);
            acc1[2 * o2 + 1] = f2fma(d1, wp.y, acc1[2 * o2 + 1]);
        }
    }

    const int p = (i0 + irow) * NSZ + j0 + 4 * jq;
    float lsum[16], lsq[16];
#pragma unroll
    for (int o = 0; o < 16; o++) {
        float b = sB[o];
        float z0 = f2lo(acc0[o]) + b;
        float z1 = f2hi(acc0[o]) + b;
        float z2 = f2lo(acc1[o]) + b;
        float z3 = f2hi(acc1[o]) + b;
        float4 zz = make_float4(z0, z1, z2, z3);
        *(float4*)&g_z[o * NNSZ + p] = zz;
        lsum[o] = (z0 + z1) + (z2 + z3);
        lsq[o]  = (z0 * z0 + z1 * z1) + (z2 * z2 + z3 * z3);
    }

#pragma unroll
    for (int o = 0; o < 16; o++) {
#pragma unroll
        for (int s = 16; s > 0; s >>= 1) {
            lsum[o] += __shfl_xor_sync(0xffffffffu, lsum[o], s);
            lsq[o]  += __shfl_xor_sync(0xffffffffu, lsq[o],  s);
        }
    }
    const int w = t >> 5, lane = t & 31;
    if (lane == 0) {
#pragma unroll
        for (int o = 0; o < 16; o++) { sRed[w][o] = lsum[o]; sRed[w][16 + o] = lsq[o]; }
    }
    __syncthreads();
    if (t < 32) {
        float v = 0.f;
#pragma unroll
        for (int b = 0; b < 8; b++) v += sRed[b][t];
        int slice = (blockIdx.y * 12 + blockIdx.x) & 7;
        if (t < 16) atomicAdd(&g_sumP[slice][t], (double)v);
        else        atomicAdd(&g_sqP[slice][t - 16], (double)v);
    }
}

// ---------------------------------------------------------------------------
// Finalize BN affine; re-zero partials.  1 block, 32 threads.
// ---------------------------------------------------------------------------
__global__ void k_fin(const float* __restrict__ gamma, const float* __restrict__ beta,
                      int layer, int H) {
    __shared__ double ss[16], qq[16];
    int t = threadIdx.x;
    if (t < 16) {
        double s = 0.0, q = 0.0;
        for (int b = 0; b < 8; b++) { s += g_sumP[b][t]; q += g_sqP[b][t]; }
        ss[t] = s; qq[t] = q;
    }
    __syncthreads();
    for (int l = t; l < 128; l += 32) {
        ((double*)g_sumP)[l] = 0.0;
        ((double*)g_sqP)[l]  = 0.0;
    }
    if (t < H) {
        double mean = ss[t] / (double)NNSZ;
        double var  = qq[t] / (double)NNSZ - mean * mean;   // biased variance
        double inv  = 1.0 / sqrt(var + 1e-5);
        float  sc   = (float)((double)gamma[t] * inv);
        g_scaleA[layer][t] = sc;
        g_shiftA[layer][t] = beta[t] - (float)mean * sc;
    }
}

// ---------------------------------------------------------------------------
// Middle layer: BN(prev)+leaky on CI planes, matmul W[CO][CI]+bias, write CO
// planes, stats.
// R10 result: no spill but regs=255 -> 1 block/SM -> occ 12.4% -> latency-
// bound at 1.8TB/s.  Fix: (a) __launch_bounds__(256, 2) pins the budget to
// 128 regs (2 blocks/SM, 16 warps); (b) 2 positions per non-unrolled loop
// iteration doubles per-warp MLP.  Live set: h/h2[32] + fsum/fsq[32] ~= 80
// regs -- fits 128 without spill.  grid 1152 x 256thr x 2pos x 4iter == NNSZ.
// ---------------------------------------------------------------------------
template <int CI, int CO>
__global__ void __launch_bounds__(256, 2) k_mid(const float* __restrict__ Wm,
                                                const float* __restrict__ bias,
                                                int layerPrev) {
    __shared__ float sW[CO * CI];
    __shared__ float sS[CI], sH[CI], sB2[CO];
    __shared__ float sRed[8][32];
    int t = threadIdx.x;
    for (int l = t; l < CO * CI; l += 256) sW[l] = Wm[l];
    if (t < CI) { sS[t] = g_scaleA[layerPrev][t]; sH[t] = g_shiftA[layerPrev][t]; }
    if (t < CO) sB2[t] = bias[t];
    __syncthreads();

    float fsum[CO], fsq[CO];
#pragma unroll
    for (int o = 0; o < CO; o++) { fsum[o] = 0.f; fsq[o] = 0.f; }

    const int base = blockIdx.x * 2048 + t;
#pragma unroll 1
    for (int it = 0; it < 4; it++) {
        const int p  = base + it * 512;      // position A (coalesced over t)
        const int p2 = p + 256;              // position B (coalesced over t)
        float h[CI], h2[CI];
#pragma unroll
        for (int c = 0; c < CI; c++) {
            float za = g_z[c * NNSZ + p];
            float zb = g_z[c * NNSZ + p2];
            float sc = sS[c], sh = sH[c];
            za = za * sc + sh; h[c]  = (za >= 0.f) ? za : 0.01f * za;
            zb = zb * sc + sh; h2[c] = (zb >= 0.f) ? zb : 0.01f * zb;
        }
#pragma unroll
        for (int o = 0; o < CO; o++) {
            float b = sB2[o];
            float a = b, a2 = b;
#pragma unroll
            for (int c = 0; c < CI; c++) {
                float w = sW[o * CI + c];
                a  += w * h[c];
                a2 += w * h2[c];
            }
            g_z[o * NNSZ + p]  = a;
            g_z[o * NNSZ + p2] = a2;
            fsum[o] += a + a2;
            fsq[o]  += a * a + a2 * a2;
        }
    }

#pragma unroll
    for (int o = 0; o < CO; o++) {
#pragma unroll
        for (int s = 16; s > 0; s >>= 1) {
            fsum[o] += __shfl_xor_sync(0xffffffffu, fsum[o], s);
            fsq[o]  += __shfl_xor_sync(0xffffffffu, fsq[o],  s);
        }
    }
    int w = t >> 5, lane = t & 31;
    if (lane == 0) {
#pragma unroll
        for (int o = 0; o < CO; o++) { sRed[w][o] = fsum[o]; sRed[w][CO + o] = fsq[o]; }
    }
    __syncthreads();
    if (t < 2 * CO) {
        float v = 0.f;
#pragma unroll
        for (int b = 0; b < 8; b++) v += sRed[b][t];
        int slice = blockIdx.x & 7;
        if (t < CO) atomicAdd(&g_sumP[slice][t], (double)v);
        else        atomicAdd(&g_sqP[slice][t - CO], (double)v);
    }
}

// ---------------------------------------------------------------------------
// Output: BN4 + leaky + dot with W5[8] + b5.  float4 x 4 iters (8 channels ->
// 32 live floats transient, no loop-carried arrays -> low pressure).
// ---------------------------------------------------------------------------
__global__ void __launch_bounds__(256, 2) k_out(const float* __restrict__ W5,
                                                const float* __restrict__ b5,
                                                float* __restrict__ out) {
    __shared__ float sS[8], sH[8], sW[8];
    __shared__ float sb;
    int t = threadIdx.x;
    if (t < 8) { sS[t] = g_scaleA[3][t]; sH[t] = g_shiftA[3][t]; sW[t] = W5[t]; }
    if (t == 0) sb = b5[0];
    __syncthreads();
    const int base = blockIdx.x * 4096 + t * 4;
#pragma unroll 1
    for (int it = 0; it < 4; it++) {
        const int p = base + it * 1024;
        float4 a = make_float4(sb, sb, sb, sb);
#pragma unroll
        for (int c = 0; c < 8; c++) {
            float4 z = *(const float4*)&g_z[c * NNSZ + p];
            float sc = sS[c], sh = sH[c], w = sW[c];
            float h;
            h = z.x * sc + sh; h = (h >= 0.f) ? h : 0.01f * h; a.x += w * h;
            h = z.y * sc + sh; h = (h >= 0.f) ? h : 0.01f * h; a.y += w * h;
            h = z.z * sc + sh; h = (h >= 0.f) ? h : 0.01f * h; a.z += w * h;
            h = z.w * sc + sh; h = (h >= 0.f) ? h : 0.01f * h; a.w += w * h;
        }
        *(float4*)&out[p] = a;
    }
}

// ---------------------------------------------------------------------------
// Launch: 10 kernels, graph-capturable, allocation-free, no syncs.
// ---------------------------------------------------------------------------
extern "C" void kernel_launch(void* const* d_in, const int* in_sizes, int n_in,
                              void* d_out, int out_size) {
    (void)in_sizes; (void)n_in; (void)out_size;
    const float* x   = (const float*)d_in[0];
    const float* W1  = (const float*)d_in[1];
    const float* b1  = (const float*)d_in[2];
    const float* g1  = (const float*)d_in[3];
    const float* be1 = (const float*)d_in[4];
    const float* W2  = (const float*)d_in[5];
    const float* b2  = (const float*)d_in[6];
    const float* g2  = (const float*)d_in[7];
    const float* be2 = (const float*)d_in[8];
    const float* W3  = (const float*)d_in[9];
    const float* b3  = (const float*)d_in[10];
    const float* g3  = (const float*)d_in[11];
    const float* be3 = (const float*)d_in[12];
    const float* W4  = (const float*)d_in[13];
    const float* b4  = (const float*)d_in[14];
    const float* g4  = (const float*)d_in[15];
    const float* be4 = (const float*)d_in[16];
    const float* W5  = (const float*)d_in[17];
    const float* b5  = (const float*)d_in[18];
    float* out = (float*)d_out;

    k_zero<<<1, 128>>>();
    k_l1<<<dim3(NSZ / 128, NSZ / 8), 256>>>(x, W1, b1);        // z1 + stats1
    k_fin<<<1, 32>>>(g1, be1, 0, 16);
    k_mid<16, 16><<<NNSZ / 2048, 256>>>(W2, b2, 0);            // z2 + stats2
    k_fin<<<1, 32>>>(g2, be2, 1, 16);
    k_mid<16, 8><<<NNSZ / 2048, 256>>>(W3, b3, 1);             // z3 + stats3
    k_fin<<<1, 32>>>(g3, be3, 2, 8);
    k_mid<8, 8><<<NNSZ / 2048, 256>>>(W4, b4, 2);              // z4 + stats4
    k_fin<<<1, 32>>>(g4, be4, 3, 8);
    k_out<<<NNSZ / 4096, 256>>>(W5, b5, out);
}

// round 12
// speedup vs baseline: 1.1346x; 1.1346x over previous
#include <cuda_runtime.h>

#define NSZ   1536
#define NNSZ  (NSZ * NSZ)          // 2,359,296  (== 1152*2048)

// ---------------------------------------------------------------------------
// Scratch (device globals -- allocation-free rule). 151 MB BSS.
// z planes SoA: g_z[c * NNSZ + p]; reused in place (widths 16->16->8->8,
// each thread reads all inputs at its position before writing the same one).
// ---------------------------------------------------------------------------
__device__ __align__(16) float  g_z[16 * NNSZ];
__device__ double g_sumP[8][16];     // sliced partials (8 copies spread atomics)
__device__ double g_sqP[8][16];
__device__ float  g_scaleA[4][16];   // BN affine: y = z*scale + shift
__device__ float  g_shiftA[4][16];

// ---- packed f32x2 helpers (sm_103a) ---------------------------------------
__device__ __forceinline__ unsigned long long f2fma(unsigned long long a,
                                                    unsigned long long b,
                                                    unsigned long long c) {
    unsigned long long d;
    asm("fma.rn.f32x2 %0, %1, %2, %3;" : "=l"(d) : "l"(a), "l"(b), "l"(c));
    return d;
}
__device__ __forceinline__ unsigned long long f2add(unsigned long long a,
                                                    unsigned long long b) {
    unsigned long long d;
    asm("add.rn.f32x2 %0, %1, %2;" : "=l"(d) : "l"(a), "l"(b));
    return d;
}
__device__ __forceinline__ unsigned long long f2dup(float x) {
    unsigned long long d;
    unsigned u = __float_as_uint(x);
    asm("mov.b64 %0, {%1, %1};" : "=l"(d) : "r"(u));
    return d;
}
__device__ __forceinline__ float f2lo(unsigned long long a) {
    return __uint_as_float((unsigned)(a & 0xFFFFFFFFull));
}
__device__ __forceinline__ float f2hi(unsigned long long a) {
    return __uint_as_float((unsigned)(a >> 32));
}

// ---------------------------------------------------------------------------
// K0: zero stats partials
// ---------------------------------------------------------------------------
__global__ void k_zero() {
    int t = threadIdx.x;
    if (t < 128) {
        ((double*)g_sumP)[t] = 0.0;
        ((double*)g_sqP)[t]  = 0.0;
    }
}

// ---------------------------------------------------------------------------
// K1: adj + layer-1 matmul + bias -> z1 (16 planes) + stats.
// (unchanged since R8 -- inferred ~115us; f32x2 packed math, 4 j-pos/thread)
// ---------------------------------------------------------------------------
__global__ void __launch_bounds__(256, 2) k_l1(const float* __restrict__ x,
                                               const float* __restrict__ W1,
                                               const float* __restrict__ b1) {
    __shared__ __align__(16) float sNXjT[64][132];  // 33.8KB, rows 528B
    __shared__ __align__(16) float sXi[8][64];      // 2KB
    __shared__ __align__(16) float sWd[64][32];     // 8KB dup'd weight pairs
    __shared__ float sB[16];
    __shared__ float sRed[8][32];

    const int t  = threadIdx.x;
    const int j0 = blockIdx.x * 128;
    const int i0 = blockIdx.y * 8;

    for (int idx = t; idx < 128 * 64; idx += 256) {
        int jj = idx >> 6, c = idx & 63;
        sNXjT[c][jj] = -x[(j0 + jj) * 64 + c];
    }
    for (int idx = t; idx < 8 * 64; idx += 256) {
        int r = idx >> 6, c = idx & 63;
        sXi[r][c] = x[(i0 + r) * 64 + c];
    }
    for (int idx = t; idx < 64 * 16; idx += 256) {
        int c = idx >> 4, o = idx & 15;
        float w = W1[o * 64 + c];
        sWd[c][2 * o]     = w;
        sWd[c][2 * o + 1] = w;
    }
    if (t < 16) sB[t] = b1[t];
    __syncthreads();

    const int jq   = t & 31;
    const int irow = t >> 5;

    unsigned long long acc0[16], acc1[16];
#pragma unroll
    for (int o = 0; o < 16; o++) { acc0[o] = 0ull; acc1[o] = 0ull; }

    const unsigned long long ABSM = 0x7FFFFFFF7FFFFFFFull;

#pragma unroll 8
    for (int c = 0; c < 64; c++) {
        unsigned long long xid = f2dup(sXi[irow][c]);
        ulonglong2 nx = *(const ulonglong2*)&sNXjT[c][4 * jq];
        unsigned long long d0 = f2add(xid, nx.x) & ABSM;
        unsigned long long d1 = f2add(xid, nx.y) & ABSM;
        const ulonglong2* wrow = (const ulonglong2*)&sWd[c][0];
#pragma unroll
        for (int o2 = 0; o2 < 8; o2++) {
            ulonglong2 wp = wrow[o2];
            acc0[2 * o2]     = f2fma(d0, wp.x, acc0[2 * o2]);
            acc1[2 * o2]     = f2fma(d1, wp.x, acc1[2 * o2]);
            acc0[2 * o2 + 1] = f2fma(d0, wp.y, acc0[2 * o2 + 1]);
            acc1[2 * o2 + 1] = f2fma(d1, wp.y, acc1[2 * o2 + 1]);
        }
    }

    const int p = (i0 + irow) * NSZ + j0 + 4 * jq;
    float lsum[16], lsq[16];
#pragma unroll
    for (int o = 0; o < 16; o++) {
        float b = sB[o];
        float z0 = f2lo(acc0[o]) + b;
        float z1 = f2hi(acc0[o]) + b;
        float z2 = f2lo(acc1[o]) + b;
        float z3 = f2hi(acc1[o]) + b;
        float4 zz = make_float4(z0, z1, z2, z3);
        *(float4*)&g_z[o * NNSZ + p] = zz;
        lsum[o] = (z0 + z1) + (z2 + z3);
        lsq[o]  = (z0 * z0 + z1 * z1) + (z2 * z2 + z3 * z3);
    }

#pragma unroll
    for (int o = 0; o < 16; o++) {
#pragma unroll
        for (int s = 16; s > 0; s >>= 1) {
            lsum[o] += __shfl_xor_sync(0xffffffffu, lsum[o], s);
            lsq[o]  += __shfl_xor_sync(0xffffffffu, lsq[o],  s);
        }
    }
    const int w = t >> 5, lane = t & 31;
    if (lane == 0) {
#pragma unroll
        for (int o = 0; o < 16; o++) { sRed[w][o] = lsum[o]; sRed[w][16 + o] = lsq[o]; }
    }
    __syncthreads();
    if (t < 32) {
        float v = 0.f;
#pragma unroll
        for (int b = 0; b < 8; b++) v += sRed[b][t];
        int slice = (blockIdx.y * 12 + blockIdx.x) & 7;
        if (t < 16) atomicAdd(&g_sumP[slice][t], (double)v);
        else        atomicAdd(&g_sqP[slice][t - 16], (double)v);
    }
}

// ---------------------------------------------------------------------------
// Finalize BN affine; re-zero partials.  1 block, 32 threads.
// ---------------------------------------------------------------------------
__global__ void k_fin(const float* __restrict__ gamma, const float* __restrict__ beta,
                      int layer, int H) {
    __shared__ double ss[16], qq[16];
    int t = threadIdx.x;
    if (t < 16) {
        double s = 0.0, q = 0.0;
        for (int b = 0; b < 8; b++) { s += g_sumP[b][t]; q += g_sqP[b][t]; }
        ss[t] = s; qq[t] = q;
    }
    __syncthreads();
    for (int l = t; l < 128; l += 32) {
        ((double*)g_sumP)[l] = 0.0;
        ((double*)g_sqP)[l]  = 0.0;
    }
    if (t < H) {
        double mean = ss[t] / (double)NNSZ;
        double var  = qq[t] / (double)NNSZ - mean * mean;   // biased variance
        double inv  = 1.0 / sqrt(var + 1e-5);
        float  sc   = (float)((double)gamma[t] * inv);
        g_scaleA[layer][t] = sc;
        g_shiftA[layer][t] = beta[t] - (float)mean * sc;
    }
}

// ---------------------------------------------------------------------------
// Middle layer: BN(prev)+leaky on CI planes, matmul W[CO][CI]+bias, write CO
// planes, stats.  NPOS positions per non-unrolled loop iteration; 8 positions
// per thread total.
// Register-model calibration across rounds (ncu evidence):
//   R8/R9: big unrolled live set -> ptxas clamps to 32 regs -> spill (790us)
//   R10:   no bound, 1-pos loop   -> 255 regs -> 1 block/SM, occ 12% (141us)
//   R11:   bound 128, 2-pos CI=16 -> live~80 + pipelining > 128 -> spill@cap
//          (273us, 833MB traffic); but CI<=8 variants got FASTER.
// => NPOS=1 for <16,16> (live~74 fits 128 w/ headroom), NPOS=2 for smaller.
// grid 1152 x 256thr x 8pos == NNSZ.
// ---------------------------------------------------------------------------
template <int CI, int CO, int NPOS>
__global__ void __launch_bounds__(256, 2) k_mid(const float* __restrict__ Wm,
                                                const float* __restrict__ bias,
                                                int layerPrev) {
    __shared__ float sW[CO * CI];
    __shared__ float sS[CI], sH[CI], sB2[CO];
    __shared__ float sRed[8][32];
    int t = threadIdx.x;
    for (int l = t; l < CO * CI; l += 256) sW[l] = Wm[l];
    if (t < CI) { sS[t] = g_scaleA[layerPrev][t]; sH[t] = g_shiftA[layerPrev][t]; }
    if (t < CO) sB2[t] = bias[t];
    __syncthreads();

    float fsum[CO], fsq[CO];
#pragma unroll
    for (int o = 0; o < CO; o++) { fsum[o] = 0.f; fsq[o] = 0.f; }

    const int base = blockIdx.x * 2048 + t;
#pragma unroll 1
    for (int it = 0; it < 8 / NPOS; it++) {
        const int p0 = base + it * (256 * NPOS);
        float h[NPOS][CI];
#pragma unroll
        for (int u = 0; u < NPOS; u++) {
#pragma unroll
            for (int c = 0; c < CI; c++) {
                float z = g_z[c * NNSZ + p0 + u * 256];
                z = z * sS[c] + sH[c];
                h[u][c] = (z >= 0.f) ? z : 0.01f * z;
            }
        }
#pragma unroll
        for (int o = 0; o < CO; o++) {
            float a[NPOS];
#pragma unroll
            for (int u = 0; u < NPOS; u++) a[u] = sB2[o];
#pragma unroll
            for (int c = 0; c < CI; c++) {
                float w = sW[o * CI + c];
#pragma unroll
                for (int u = 0; u < NPOS; u++) a[u] += w * h[u][c];
            }
#pragma unroll
            for (int u = 0; u < NPOS; u++) {
                g_z[o * NNSZ + p0 + u * 256] = a[u];
                fsum[o] += a[u];
                fsq[o]  += a[u] * a[u];
            }
        }
    }

#pragma unroll
    for (int o = 0; o < CO; o++) {
#pragma unroll
        for (int s = 16; s > 0; s >>= 1) {
            fsum[o] += __shfl_xor_sync(0xffffffffu, fsum[o], s);
            fsq[o]  += __shfl_xor_sync(0xffffffffu, fsq[o],  s);
        }
    }
    int w = t >> 5, lane = t & 31;
    if (lane == 0) {
#pragma unroll
        for (int o = 0; o < CO; o++) { sRed[w][o] = fsum[o]; sRed[w][CO + o] = fsq[o]; }
    }
    __syncthreads();
    if (t < 2 * CO) {
        float v = 0.f;
#pragma unroll
        for (int b = 0; b < 8; b++) v += sRed[b][t];
        int slice = blockIdx.x & 7;
        if (t < CO) atomicAdd(&g_sumP[slice][t], (double)v);
        else        atomicAdd(&g_sqP[slice][t - CO], (double)v);
    }
}

// ---------------------------------------------------------------------------
// Output: BN4 + leaky + dot with W5[8] + b5.  float4 x 4 iters (8 channels ->
// 32 live floats transient, no loop-carried arrays -> low pressure).
// ---------------------------------------------------------------------------
__global__ void __launch_bounds__(256, 2) k_out(const float* __restrict__ W5,
                                                const float* __restrict__ b5,
                                                float* __restrict__ out) {
    __shared__ float sS[8], sH[8], sW[8];
    __shared__ float sb;
    int t = threadIdx.x;
    if (t < 8) { sS[t] = g_scaleA[3][t]; sH[t] = g_shiftA[3][t]; sW[t] = W5[t]; }
    if (t == 0) sb = b5[0];
    __syncthreads();
    const int base = blockIdx.x * 4096 + t * 4;
#pragma unroll 1
    for (int it = 0; it < 4; it++) {
        const int p = base + it * 1024;
        float4 a = make_float4(sb, sb, sb, sb);
#pragma unroll
        for (int c = 0; c < 8; c++) {
            float4 z = *(const float4*)&g_z[c * NNSZ + p];
            float sc = sS[c], sh = sH[c], w = sW[c];
            float h;
            h = z.x * sc + sh; h = (h >= 0.f) ? h : 0.01f * h; a.x += w * h;
            h = z.y * sc + sh; h = (h >= 0.f) ? h : 0.01f * h; a.y += w * h;
            h = z.z * sc + sh; h = (h >= 0.f) ? h : 0.01f * h; a.z += w * h;
            h = z.w * sc + sh; h = (h >= 0.f) ? h : 0.01f * h; a.w += w * h;
        }
        *(float4*)&out[p] = a;
    }
}

// ---------------------------------------------------------------------------
// Launch: 10 kernels, graph-capturable, allocation-free, no syncs.
// ---------------------------------------------------------------------------
extern "C" void kernel_launch(void* const* d_in, const int* in_sizes, int n_in,
                              void* d_out, int out_size) {
    (void)in_sizes; (void)n_in; (void)out_size;
    const float* x   = (const float*)d_in[0];
    const float* W1  = (const float*)d_in[1];
    const float* b1  = (const float*)d_in[2];
    const float* g1  = (const float*)d_in[3];
    const float* be1 = (const float*)d_in[4];
    const float* W2  = (const float*)d_in[5];
    const float* b2  = (const float*)d_in[6];
    const float* g2  = (const float*)d_in[7];
    const float* be2 = (const float*)d_in[8];
    const float* W3  = (const float*)d_in[9];
    const float* b3  = (const float*)d_in[10];
    const float* g3  = (const float*)d_in[11];
    const float* be3 = (const float*)d_in[12];
    const float* W4  = (const float*)d_in[13];
    const float* b4  = (const float*)d_in[14];
    const float* g4  = (const float*)d_in[15];
    const float* be4 = (const float*)d_in[16];
    const float* W5  = (const float*)d_in[17];
    const float* b5  = (const float*)d_in[18];
    float* out = (float*)d_out;

    k_zero<<<1, 128>>>();
    k_l1<<<dim3(NSZ / 128, NSZ / 8), 256>>>(x, W1, b1);        // z1 + stats1
    k_fin<<<1, 32>>>(g1, be1, 0, 16);
    k_mid<16, 16, 1><<<NNSZ / 2048, 256>>>(W2, b2, 0);         // z2 + stats2
    k_fin<<<1, 32>>>(g2, be2, 1, 16);
    k_mid<16, 8, 2><<<NNSZ / 2048, 256>>>(W3, b3, 1);          // z3 + stats3
    k_fin<<<1, 32>>>(g3, be3, 2, 8);
    k_mid<8, 8, 2><<<NNSZ / 2048, 256>>>(W4, b4, 2);           // z4 + stats4
    k_fin<<<1, 32>>>(g4, be4, 3, 8);
    k_out<<<NNSZ / 4096, 256>>>(W5, b5, out);
}

// round 14
// speedup vs baseline: 1.4341x; 1.2641x over previous
#include <cuda_runtime.h>

#define NSZ   1536
#define NNSZ  (NSZ * NSZ)          // 2,359,296  (== 9216*256 == 1152*2048)

// ---------------------------------------------------------------------------
// Scratch (device globals -- allocation-free rule). 151 MB BSS.
// z planes SoA: g_z[c * NNSZ + p]; reused in place (widths 16->16->8->8,
// each thread reads all inputs at its position before writing the same one).
// ---------------------------------------------------------------------------
__device__ __align__(16) float  g_z[16 * NNSZ];
__device__ double g_sumP[8][16];     // sliced partials (8 copies spread atomics)
__device__ double g_sqP[8][16];
__device__ float  g_scaleA[4][16];   // BN affine: y = z*scale + shift
__device__ float  g_shiftA[4][16];

// ---- packed f32x2 helpers (sm_103a) ---------------------------------------
__device__ __forceinline__ unsigned long long f2fma(unsigned long long a,
                                                    unsigned long long b,
                                                    unsigned long long c) {
    unsigned long long d;
    asm("fma.rn.f32x2 %0, %1, %2, %3;" : "=l"(d) : "l"(a), "l"(b), "l"(c));
    return d;
}
__device__ __forceinline__ unsigned long long f2add(unsigned long long a,
                                                    unsigned long long b) {
    unsigned long long d;
    asm("add.rn.f32x2 %0, %1, %2;" : "=l"(d) : "l"(a), "l"(b));
    return d;
}
__device__ __forceinline__ unsigned long long f2dup(float x) {
    unsigned long long d;
    unsigned u = __float_as_uint(x);
    asm("mov.b64 %0, {%1, %1};" : "=l"(d) : "r"(u));
    return d;
}
__device__ __forceinline__ float f2lo(unsigned long long a) {
    return __uint_as_float((unsigned)(a & 0xFFFFFFFFull));
}
__device__ __forceinline__ float f2hi(unsigned long long a) {
    return __uint_as_float((unsigned)(a >> 32));
}

// ---------------------------------------------------------------------------
// K0: zero stats partials
// ---------------------------------------------------------------------------
__global__ void k_zero() {
    int t = threadIdx.x;
    if (t < 128) {
        ((double*)g_sumP)[t] = 0.0;
        ((double*)g_sqP)[t]  = 0.0;
    }
}

// ---------------------------------------------------------------------------
// K1: adj + layer-1 matmul + bias -> z1 (16 planes) + stats.
// (unchanged since R8 -- inferred ~115us; f32x2 packed math, 4 j-pos/thread)
// ---------------------------------------------------------------------------
__global__ void __launch_bounds__(256, 2) k_l1(const float* __restrict__ x,
                                               const float* __restrict__ W1,
                                               const float* __restrict__ b1) {
    __shared__ __align__(16) float sNXjT[64][132];  // 33.8KB, rows 528B
    __shared__ __align__(16) float sXi[8][64];      // 2KB
    __shared__ __align__(16) float sWd[64][32];     // 8KB dup'd weight pairs
    __shared__ float sB[16];
    __shared__ float sRed[8][32];

    const int t  = threadIdx.x;
    const int j0 = blockIdx.x * 128;
    const int i0 = blockIdx.y * 8;

    for (int idx = t; idx < 128 * 64; idx += 256) {
        int jj = idx >> 6, c = idx & 63;
        sNXjT[c][jj] = -x[(j0 + jj) * 64 + c];
    }
    for (int idx = t; idx < 8 * 64; idx += 256) {
        int r = idx >> 6, c = idx & 63;
        sXi[r][c] = x[(i0 + r) * 64 + c];
    }
    for (int idx = t; idx < 64 * 16; idx += 256) {
        int c = idx >> 4, o = idx & 15;
        float w = W1[o * 64 + c];
        sWd[c][2 * o]     = w;
        sWd[c][2 * o + 1] = w;
    }
    if (t < 16) sB[t] = b1[t];
    __syncthreads();

    const int jq   = t & 31;
    const int irow = t >> 5;

    unsigned long long acc0[16], acc1[16];
#pragma unroll
    for (int o = 0; o < 16; o++) { acc0[o] = 0ull; acc1[o] = 0ull; }

    const unsigned long long ABSM = 0x7FFFFFFF7FFFFFFFull;

#pragma unroll 8
    for (int c = 0; c < 64; c++) {
        unsigned long long xid = f2dup(sXi[irow][c]);
        ulonglong2 nx = *(const ulonglong2*)&sNXjT[c][4 * jq];
        unsigned long long d0 = f2add(xid, nx.x) & ABSM;
        unsigned long long d1 = f2add(xid, nx.y) & ABSM;
        const ulonglong2* wrow = (const ulonglong2*)&sWd[c][0];
#pragma unroll
        for (int o2 = 0; o2 < 8; o2++) {
            ulonglong2 wp = wrow[o2];
            acc0[2 * o2]     = f2fma(d0, wp.x, acc0[2 * o2]);
            acc1[2 * o2]     = f2fma(d1, wp.x, acc1[2 * o2]);
            acc0[2 * o2 + 1] = f2fma(d0, wp.y, acc0[2 * o2 + 1]);
            acc1[2 * o2 + 1] = f2fma(d1, wp.y, acc1[2 * o2 + 1]);
        }
    }

    const int p = (i0 + irow) * NSZ + j0 + 4 * jq;
    float lsum[16], lsq[16];
#pragma unroll
    for (int o = 0; o < 16; o++) {
        float b = sB[o];
        float z0 = f2lo(acc0[o]) + b;
        float z1 = f2hi(acc0[o]) + b;
        float z2 = f2lo(acc1[o]) + b;
        float z3 = f2hi(acc1[o]) + b;
        float4 zz = make_float4(z0, z1, z2, z3);
        *(float4*)&g_z[o * NNSZ + p] = zz;
        lsum[o] = (z0 + z1) + (z2 + z3);
        lsq[o]  = (z0 * z0 + z1 * z1) + (z2 * z2 + z3 * z3);
    }

#pragma unroll
    for (int o = 0; o < 16; o++) {
#pragma unroll
        for (int s = 16; s > 0; s >>= 1) {
            lsum[o] += __shfl_xor_sync(0xffffffffu, lsum[o], s);
            lsq[o]  += __shfl_xor_sync(0xffffffffu, lsq[o],  s);
        }
    }
    const int w = t >> 5, lane = t & 31;
    if (lane == 0) {
#pragma unroll
        for (int o = 0; o < 16; o++) { sRed[w][o] = lsum[o]; sRed[w][16 + o] = lsq[o]; }
    }
    __syncthreads();
    if (t < 32) {
        float v = 0.f;
#pragma unroll
        for (int b = 0; b < 8; b++) v += sRed[b][t];
        int slice = (blockIdx.y * 12 + blockIdx.x) & 7;
        if (t < 16) atomicAdd(&g_sumP[slice][t], (double)v);
        else        atomicAdd(&g_sqP[slice][t - 16], (double)v);
    }
}

// ---------------------------------------------------------------------------
// Finalize BN affine; re-zero partials.  1 block, 32 threads.
// ---------------------------------------------------------------------------
__global__ void k_fin(const float* __restrict__ gamma, const float* __restrict__ beta,
                      int layer, int H) {
    __shared__ double ss[16], qq[16];
    int t = threadIdx.x;
    if (t < 16) {
        double s = 0.0, q = 0.0;
        for (int b = 0; b < 8; b++) { s += g_sumP[b][t]; q += g_sqP[b][t]; }
        ss[t] = s; qq[t] = q;
    }
    __syncthreads();
    for (int l = t; l < 128; l += 32) {
        ((double*)g_sumP)[l] = 0.0;
        ((double*)g_sqP)[l]  = 0.0;
    }
    if (t < H) {
        double mean = ss[t] / (double)NNSZ;
        double var  = qq[t] / (double)NNSZ - mean * mean;   // biased variance
        double inv  = 1.0 / sqrt(var + 1e-5);
        float  sc   = (float)((double)gamma[t] * inv);
        g_scaleA[layer][t] = sc;
        g_shiftA[layer][t] = beta[t] - (float)mean * sc;
    }
}

// ---------------------------------------------------------------------------
// Layer-2 (16->16): EXACT R6 structure -- the empirically fastest variant of
// this kernel (regs=74, 100.6us measured).  One position per thread,
// straight-line body, NO per-thread position loop, NO blocks-per-SM bound.
// Five structural variants (R8-R12) of SHFL amortization all lost more to
// ptxas register pathology (clamp->spill / balloon->occ / cap->spill) than
// the ~40us of SHFL they saved.  grid 9216 x 256 == NNSZ.
// ---------------------------------------------------------------------------
__global__ void __launch_bounds__(256) k_mid1(const float* __restrict__ Wm,
                                              const float* __restrict__ bias) {
    __shared__ float sW[16 * 16];
    __shared__ float sS[16], sH[16], sB2[16];
    __shared__ float sRed[8][32];
    int t = threadIdx.x;
    if (t < 256) sW[t] = Wm[t];
    if (t < 16) { sS[t] = g_scaleA[0][t]; sH[t] = g_shiftA[0][t]; }
    if (t < 16) sB2[t] = bias[t];
    __syncthreads();

    int p = blockIdx.x * 256 + t;        // exact: 9216*256 == NNSZ
    float h[16];
#pragma unroll
    for (int c = 0; c < 16; c++) {
        float z = g_z[c * NNSZ + p];
        z = z * sS[c] + sH[c];
        h[c] = (z >= 0.f) ? z : 0.01f * z;
    }
    float acc[16], sq[16];
#pragma unroll
    for (int o = 0; o < 16; o++) {
        float a = sB2[o];
#pragma unroll
        for (int c = 0; c < 16; c++) a += sW[o * 16 + c] * h[c];
        g_z[o * NNSZ + p] = a;
        acc[o] = a; sq[o] = a * a;
    }
#pragma unroll
    for (int o = 0; o < 16; o++) {
#pragma unroll
        for (int s = 16; s > 0; s >>= 1) {
            acc[o] += __shfl_xor_sync(0xffffffffu, acc[o], s);
            sq[o]  += __shfl_xor_sync(0xffffffffu, sq[o],  s);
        }
    }
    int w = t >> 5, lane = t & 31;
    if (lane == 0) {
#pragma unroll
        for (int o = 0; o < 16; o++) { sRed[w][o] = acc[o]; sRed[w][16 + o] = sq[o]; }
    }
    __syncthreads();
    if (t < 32) {
        float v = 0.f;
#pragma unroll
        for (int b = 0; b < 8; b++) v += sRed[b][t];
        int slice = blockIdx.x & 7;
        if (t < 16) atomicAdd(&g_sumP[slice][t], (double)v);
        else        atomicAdd(&g_sqP[slice][t - 16], (double)v);
    }
}

// ---------------------------------------------------------------------------
// Later middle layers (CI<=16 in, CO<=8 out): NPOS=2 positions per
// non-unrolled iteration -- measurably improved in R11/R12 (live set fits the
// 128-reg cap with headroom at these widths).  grid 1152 x 256 x 2 x 4 == NNSZ.
// ---------------------------------------------------------------------------
template <int CI, int CO, int NPOS>
__global__ void __launch_bounds__(256, 2) k_mid(const float* __restrict__ Wm,
                                                const float* __restrict__ bias,
                                                int layerPrev) {
    __shared__ float sW[CO * CI];
    __shared__ float sS[CI], sH[CI], sB2[CO];
    __shared__ float sRed[8][32];
    int t = threadIdx.x;
    for (int l = t; l < CO * CI; l += 256) sW[l] = Wm[l];
    if (t < CI) { sS[t] = g_scaleA[layerPrev][t]; sH[t] = g_shiftA[layerPrev][t]; }
    if (t < CO) sB2[t] = bias[t];
    __syncthreads();

    float fsum[CO], fsq[CO];
#pragma unroll
    for (int o = 0; o < CO; o++) { fsum[o] = 0.f; fsq[o] = 0.f; }

    const int base = blockIdx.x * 2048 + t;
#pragma unroll 1
    for (int it = 0; it < 8 / NPOS; it++) {
        const int p0 = base + it * (256 * NPOS);
        float h[NPOS][CI];
#pragma unroll
        for (int u = 0; u < NPOS; u++) {
#pragma unroll
            for (int c = 0; c < CI; c++) {
                float z = g_z[c * NNSZ + p0 + u * 256];
                z = z * sS[c] + sH[c];
                h[u][c] = (z >= 0.f) ? z : 0.01f * z;
            }
        }
#pragma unroll
        for (int o = 0; o < CO; o++) {
            float a[NPOS];
#pragma unroll
            for (int u = 0; u < NPOS; u++) a[u] = sB2[o];
#pragma unroll
            for (int c = 0; c < CI; c++) {
                float w = sW[o * CI + c];
#pragma unroll
                for (int u = 0; u < NPOS; u++) a[u] += w * h[u][c];
            }
#pragma unroll
            for (int u = 0; u < NPOS; u++) {
                g_z[o * NNSZ + p0 + u * 256] = a[u];
                fsum[o] += a[u];
                fsq[o]  += a[u] * a[u];
            }
        }
    }

#pragma unroll
    for (int o = 0; o < CO; o++) {
#pragma unroll
        for (int s = 16; s > 0; s >>= 1) {
            fsum[o] += __shfl_xor_sync(0xffffffffu, fsum[o], s);
            fsq[o]  += __shfl_xor_sync(0xffffffffu, fsq[o],  s);
        }
    }
    int w = t >> 5, lane = t & 31;
    if (lane == 0) {
#pragma unroll
        for (int o = 0; o < CO; o++) { sRed[w][o] = fsum[o]; sRed[w][CO + o] = fsq[o]; }
    }
    __syncthreads();
    if (t < 2 * CO) {
        float v = 0.f;
#pragma unroll
        for (int b = 0; b < 8; b++) v += sRed[b][t];
        int slice = blockIdx.x & 7;
        if (t < CO) atomicAdd(&g_sumP[slice][t], (double)v);
        else        atomicAdd(&g_sqP[slice][t - CO], (double)v);
    }
}

// ---------------------------------------------------------------------------
// Output: BN4 + leaky + dot with W5[8] + b5.  float4 x 4 iters (8 channels ->
// 32 live floats transient, no loop-carried arrays -> low pressure).
// ---------------------------------------------------------------------------
__global__ void __launch_bounds__(256, 2) k_out(const float* __restrict__ W5,
                                                const float* __restrict__ b5,
                                                float* __restrict__ out) {
    __shared__ float sS[8], sH[8], sW[8];
    __shared__ float sb;
    int t = threadIdx.x;
    if (t < 8) { sS[t] = g_scaleA[3][t]; sH[t] = g_shiftA[3][t]; sW[t] = W5[t]; }
    if (t == 0) sb = b5[0];
    __syncthreads();
    const int base = blockIdx.x * 4096 + t * 4;
#pragma unroll 1
    for (int it = 0; it < 4; it++) {
        const int p = base + it * 1024;
        float4 a = make_float4(sb, sb, sb, sb);
#pragma unroll
        for (int c = 0; c < 8; c++) {
            float4 z = *(const float4*)&g_z[c * NNSZ + p];
            float sc = sS[c], sh = sH[c], w = sW[c];
            float h;
            h = z.x * sc + sh; h = (h >= 0.f) ? h : 0.01f * h; a.x += w * h;
            h = z.y * sc + sh; h = (h >= 0.f) ? h : 0.01f * h; a.y += w * h;
            h = z.z * sc + sh; h = (h >= 0.f) ? h : 0.01f * h; a.z += w * h;
            h = z.w * sc + sh; h = (h >= 0.f) ? h : 0.01f * h; a.w += w * h;
        }
        *(float4*)&out[p] = a;
    }
}

// ---------------------------------------------------------------------------
// Launch: 10 kernels, graph-capturable, allocation-free, no syncs.
// ---------------------------------------------------------------------------
extern "C" void kernel_launch(void* const* d_in, const int* in_sizes, int n_in,
                              void* d_out, int out_size) {
    (void)in_sizes; (void)n_in; (void)out_size;
    const float* x   = (const float*)d_in[0];
    const float* W1  = (const float*)d_in[1];
    const float* b1  = (const float*)d_in[2];
    const float* g1  = (const float*)d_in[3];
    const float* be1 = (const float*)d_in[4];
    const float* W2  = (const float*)d_in[5];
    const float* b2  = (const float*)d_in[6];
    const float* g2  = (const float*)d_in[7];
    const float* be2 = (const float*)d_in[8];
    const float* W3  = (const float*)d_in[9];
    const float* b3  = (const float*)d_in[10];
    const float* g3  = (const float*)d_in[11];
    const float* be3 = (const float*)d_in[12];
    const float* W4  = (const float*)d_in[13];
    const float* b4  = (const float*)d_in[14];
    const float* g4  = (const float*)d_in[15];
    const float* be4 = (const float*)d_in[16];
    const float* W5  = (const float*)d_in[17];
    const float* b5  = (const float*)d_in[18];
    float* out = (float*)d_out;

    k_zero<<<1, 128>>>();
    k_l1<<<dim3(NSZ / 128, NSZ / 8), 256>>>(x, W1, b1);        // z1 + stats1
    k_fin<<<1, 32>>>(g1, be1, 0, 16);
    k_mid1<<<NNSZ / 256, 256>>>(W2, b2);                       // z2 + stats2 (R6 shape)
    k_fin<<<1, 32>>>(g2, be2, 1, 16);
    k_mid<16, 8, 2><<<NNSZ / 2048, 256>>>(W3, b3, 1);          // z3 + stats3
    k_fin<<<1, 32>>>(g3, be3, 2, 8);
    k_mid<8, 8, 2><<<NNSZ / 2048, 256>>>(W4, b4, 2);           // z4 + stats4
    k_fin<<<1, 32>>>(g4, be4, 3, 8);
    k_out<<<NNSZ / 4096, 256>>>(W5, b5, out);
}

// round 16
// speedup vs baseline: 1.4899x; 1.0389x over previous
#include <cuda_runtime.h>

#define NSZ   1536
#define NNSZ  (NSZ * NSZ)          // 2,359,296  (== 9216*256 == 4608*512)

// ---------------------------------------------------------------------------
// Scratch (device globals -- allocation-free rule). 151 MB BSS.
// ---------------------------------------------------------------------------
__device__ __align__(16) float  g_z[16 * NNSZ];
__device__ double g_sumP[8][16];     // sliced partials (8 copies spread atomics)
__device__ double g_sqP[8][16];
__device__ float  g_scaleA[4][16];   // BN affine: y = z*scale + shift
__device__ float  g_shiftA[4][16];

// ---- packed f32x2 helpers (sm_103a) ---------------------------------------
__device__ __forceinline__ unsigned long long f2fma(unsigned long long a,
                                                    unsigned long long b,
                                                    unsigned long long c) {
    unsigned long long d;
    asm("fma.rn.f32x2 %0, %1, %2, %3;" : "=l"(d) : "l"(a), "l"(b), "l"(c));
    return d;
}
__device__ __forceinline__ unsigned long long f2add(unsigned long long a,
                                                    unsigned long long b) {
    unsigned long long d;
    asm("add.rn.f32x2 %0, %1, %2;" : "=l"(d) : "l"(a), "l"(b));
    return d;
}
__device__ __forceinline__ unsigned long long f2dup(float x) {
    unsigned long long d;
    unsigned u = __float_as_uint(x);
    asm("mov.b64 %0, {%1, %1};" : "=l"(d) : "r"(u));
    return d;
}
__device__ __forceinline__ unsigned long long f2pack(float lo, float hi) {
    unsigned long long d;
    asm("mov.b64 %0, {%1, %2};" : "=l"(d) : "f"(lo), "f"(hi));
    return d;
}
__device__ __forceinline__ float f2lo(unsigned long long a) {
    return __uint_as_float((unsigned)(a & 0xFFFFFFFFull));
}
__device__ __forceinline__ float f2hi(unsigned long long a) {
    return __uint_as_float((unsigned)(a >> 32));
}

// ---------------------------------------------------------------------------
// K0: zero stats partials
// ---------------------------------------------------------------------------
__global__ void k_zero() {
    int t = threadIdx.x;
    if (t < 128) {
        ((double*)g_sumP)[t] = 0.0;
        ((double*)g_sqP)[t]  = 0.0;
    }
}

// ---------------------------------------------------------------------------
// K1: adj + layer-1 matmul + bias -> z1 (16 planes) + stats.
// f32x2 packed math, 4 j-pos/thread.  Inner unroll reduced 8->4 this round:
// under the 128-reg cap the 8-deep body (acc=64 + ~45 pipeline temps) can
// spill at the cap (R11 mode); unroll 4 halves the pipeline temps.
// ---------------------------------------------------------------------------
__global__ void __launch_bounds__(256, 2) k_l1(const float* __restrict__ x,
                                               const float* __restrict__ W1,
                                               const float* __restrict__ b1) {
    __shared__ __align__(16) float sNXjT[64][132];  // 33.8KB, rows 528B
    __shared__ __align__(16) float sXi[8][64];      // 2KB
    __shared__ __align__(16) float sWd[64][32];     // 8KB dup'd weight pairs
    __shared__ float sB[16];
    __shared__ float sRed[8][32];

    const int t  = threadIdx.x;
    const int j0 = blockIdx.x * 128;
    const int i0 = blockIdx.y * 8;

    for (int idx = t; idx < 128 * 64; idx += 256) {
        int jj = idx >> 6, c = idx & 63;
        sNXjT[c][jj] = -x[(j0 + jj) * 64 + c];
    }
    for (int idx = t; idx < 8 * 64; idx += 256) {
        int r = idx >> 6, c = idx & 63;
        sXi[r][c] = x[(i0 + r) * 64 + c];
    }
    for (int idx = t; idx < 64 * 16; idx += 256) {
        int c = idx >> 4, o = idx & 15;
        float w = W1[o * 64 + c];
        sWd[c][2 * o]     = w;
        sWd[c][2 * o + 1] = w;
    }
    if (t < 16) sB[t] = b1[t];
    __syncthreads();

    const int jq   = t & 31;
    const int irow = t >> 5;

    unsigned long long acc0[16], acc1[16];
#pragma unroll
    for (int o = 0; o < 16; o++) { acc0[o] = 0ull; acc1[o] = 0ull; }

    const unsigned long long ABSM = 0x7FFFFFFF7FFFFFFFull;

#pragma unroll 4
    for (int c = 0; c < 64; c++) {
        unsigned long long xid = f2dup(sXi[irow][c]);
        ulonglong2 nx = *(const ulonglong2*)&sNXjT[c][4 * jq];
        unsigned long long d0 = f2add(xid, nx.x) & ABSM;
        unsigned long long d1 = f2add(xid, nx.y) & ABSM;
        const ulonglong2* wrow = (const ulonglong2*)&sWd[c][0];
#pragma unroll
        for (int o2 = 0; o2 < 8; o2++) {
            ulonglong2 wp = wrow[o2];
            acc0[2 * o2]     = f2fma(d0, wp.x, acc0[2 * o2]);
            acc1[2 * o2]     = f2fma(d1, wp.x, acc1[2 * o2]);
            acc0[2 * o2 + 1] = f2fma(d0, wp.y, acc0[2 * o2 + 1]);
            acc1[2 * o2 + 1] = f2fma(d1, wp.y, acc1[2 * o2 + 1]);
        }
    }

    const int p = (i0 + irow) * NSZ + j0 + 4 * jq;
    float lsum[16], lsq[16];
#pragma unroll
    for (int o = 0; o < 16; o++) {
        float b = sB[o];
        float z0 = f2lo(acc0[o]) + b;
        float z1 = f2hi(acc0[o]) + b;
        float z2 = f2lo(acc1[o]) + b;
        float z3 = f2hi(acc1[o]) + b;
        float4 zz = make_float4(z0, z1, z2, z3);
        *(float4*)&g_z[o * NNSZ + p] = zz;
        lsum[o] = (z0 + z1) + (z2 + z3);
        lsq[o]  = (z0 * z0 + z1 * z1) + (z2 * z2 + z3 * z3);
    }

#pragma unroll
    for (int o = 0; o < 16; o++) {
#pragma unroll
        for (int s = 16; s > 0; s >>= 1) {
            lsum[o] += __shfl_xor_sync(0xffffffffu, lsum[o], s);
            lsq[o]  += __shfl_xor_sync(0xffffffffu, lsq[o],  s);
        }
    }
    const int w = t >> 5, lane = t & 31;
    if (lane == 0) {
#pragma unroll
        for (int o = 0; o < 16; o++) { sRed[w][o] = lsum[o]; sRed[w][16 + o] = lsq[o]; }
    }
    __syncthreads();
    if (t < 32) {
        float v = 0.f;
#pragma unroll
        for (int b = 0; b < 8; b++) v += sRed[b][t];
        int slice = (blockIdx.y * 12 + blockIdx.x) & 7;
        if (t < 16) atomicAdd(&g_sumP[slice][t], (double)v);
        else        atomicAdd(&g_sqP[slice][t - 16], (double)v);
    }
}

// ---------------------------------------------------------------------------
// Finalize BN affine; re-zero partials.  1 block, 32 threads.
// ---------------------------------------------------------------------------
__global__ void k_fin(const float* __restrict__ gamma, const float* __restrict__ beta,
                      int layer, int H) {
    __shared__ double ss[16], qq[16];
    int t = threadIdx.x;
    if (t < 16) {
        double s = 0.0, q = 0.0;
        for (int b = 0; b < 8; b++) { s += g_sumP[b][t]; q += g_sqP[b][t]; }
        ss[t] = s; qq[t] = q;
    }
    __syncthreads();
    for (int l = t; l < 128; l += 32) {
        ((double*)g_sumP)[l] = 0.0;
        ((double*)g_sqP)[l]  = 0.0;
    }
    if (t < H) {
        double mean = ss[t] / (double)NNSZ;
        double var  = qq[t] / (double)NNSZ - mean * mean;   // biased variance
        double inv  = 1.0 / sqrt(var + 1e-5);
        float  sc   = (float)((double)gamma[t] * inv);
        g_scaleA[layer][t] = sc;
        g_shiftA[layer][t] = beta[t] - (float)mean * sc;
    }
}

// ---------------------------------------------------------------------------
// Layer-2 (16->16): f32x2 version of the proven R6 straight-line shape.
// 2 consecutive positions packed per thread; NO position loop (the only
// structure that has never triggered ptxas reg pathology).  Every weight
// LDS.64 + FFMA2 serves both positions; BN is one packed FMA; stats SHFLs
// amortized 2x.  All loads/stores are coalesced 8B (float2/u64).
// Per-element math identical to scalar version (same fma chain order).
// Live set ~= h[16]*u64(32) + lsum/lsq(32) + misc ~= 90 regs.
// grid 4608 x 256thr x 2pos == NNSZ.
// ---------------------------------------------------------------------------
__global__ void __launch_bounds__(256) k_mid1(const float* __restrict__ Wm,
                                              const float* __restrict__ bias) {
    __shared__ unsigned long long sW2[16][16];   // {w,w} pairs, [o][c]
    __shared__ unsigned long long sS2[16], sH2[16], sB2[16];
    __shared__ float sRed[8][32];
    int t = threadIdx.x;
    {   // 256 threads fill 256 (o,c) weight pairs
        int o = t >> 4, c = t & 15;
        float w = Wm[o * 16 + c];
        sW2[o][c] = f2dup(w);
    }
    if (t < 16) {
        sS2[t] = f2dup(g_scaleA[0][t]);
        sH2[t] = f2dup(g_shiftA[0][t]);
        sB2[t] = f2dup(bias[t]);
    }
    __syncthreads();

    const int p = blockIdx.x * 512 + 2 * t;      // 2 consecutive positions

    unsigned long long h[16];
#pragma unroll
    for (int c = 0; c < 16; c++) {
        unsigned long long z = *(const unsigned long long*)&g_z[c * NNSZ + p];
        z = f2fma(z, sS2[c], sH2[c]);            // BN affine, packed
        float lo = f2lo(z), hi = f2hi(z);        // leaky (scalar halves)
        lo = (lo >= 0.f) ? lo : 0.01f * lo;
        hi = (hi >= 0.f) ? hi : 0.01f * hi;
        h[c] = f2pack(lo, hi);
    }

    float lsum[16], lsq[16];
#pragma unroll
    for (int o = 0; o < 16; o++) {
        unsigned long long acc = sB2[o];
#pragma unroll
        for (int c = 0; c < 16; c++) acc = f2fma(h[c], sW2[o][c], acc);
        *(unsigned long long*)&g_z[o * NNSZ + p] = acc;   // STG.64, coalesced
        float a0 = f2lo(acc), a1 = f2hi(acc);
        lsum[o] = a0 + a1;
        lsq[o]  = a0 * a0 + a1 * a1;
    }

#pragma unroll
    for (int o = 0; o < 16; o++) {
#pragma unroll
        for (int s = 16; s > 0; s >>= 1) {
            lsum[o] += __shfl_xor_sync(0xffffffffu, lsum[o], s);
            lsq[o]  += __shfl_xor_sync(0xffffffffu, lsq[o],  s);
        }
    }
    int w = t >> 5, lane = t & 31;
    if (lane == 0) {
#pragma unroll
        for (int o = 0; o < 16; o++) { sRed[w][o] = lsum[o]; sRed[w][16 + o] = lsq[o]; }
    }
    __syncthreads();
    if (t < 32) {
        float v = 0.f;
#pragma unroll
        for (int b = 0; b < 8; b++) v += sRed[b][t];
        int slice = blockIdx.x & 7;
        if (t < 16) atomicAdd(&g_sumP[slice][t], (double)v);
        else        atomicAdd(&g_sqP[slice][t - 16], (double)v);
    }
}

// ---------------------------------------------------------------------------
// Later middle layers (CI<=16 in, CO<=8 out): NPOS=2 positions per
// non-unrolled iteration (proven in R11/R12 at these widths).
// grid 1152 x 256 x 2 x 4 == NNSZ.
// ---------------------------------------------------------------------------
template <int CI, int CO, int NPOS>
__global__ void __launch_bounds__(256, 2) k_mid(const float* __restrict__ Wm,
                                                const float* __restrict__ bias,
                                                int layerPrev) {
    __shared__ float sW[CO * CI];
    __shared__ float sS[CI], sH[CI], sB2[CO];
    __shared__ float sRed[8][32];
    int t = threadIdx.x;
    for (int l = t; l < CO * CI; l += 256) sW[l] = Wm[l];
    if (t < CI) { sS[t] = g_scaleA[layerPrev][t]; sH[t] = g_shiftA[layerPrev][t]; }
    if (t < CO) sB2[t] = bias[t];
    __syncthreads();

    float fsum[CO], fsq[CO];
#pragma unroll
    for (int o = 0; o < CO; o++) { fsum[o] = 0.f; fsq[o] = 0.f; }

    const int base = blockIdx.x * 2048 + t;
#pragma unroll 1
    for (int it = 0; it < 8 / NPOS; it++) {
        const int p0 = base + it * (256 * NPOS);
        float h[NPOS][CI];
#pragma unroll
        for (int u = 0; u < NPOS; u++) {
#pragma unroll
            for (int c = 0; c < CI; c++) {
                float z = g_z[c * NNSZ + p0 + u * 256];
                z = z * sS[c] + sH[c];
                h[u][c] = (z >= 0.f) ? z : 0.01f * z;
            }
        }
#pragma unroll
        for (int o = 0; o < CO; o++) {
            float a[NPOS];
#pragma unroll
            for (int u = 0; u < NPOS; u++) a[u] = sB2[o];
#pragma unroll
            for (int c = 0; c < CI; c++) {
                float w = sW[o * CI + c];
#pragma unroll
                for (int u = 0; u < NPOS; u++) a[u] += w * h[u][c];
            }
#pragma unroll
            for (int u = 0; u < NPOS; u++) {
                g_z[o * NNSZ + p0 + u * 256] = a[u];
                fsum[o] += a[u];
                fsq[o]  += a[u] * a[u];
            }
        }
    }

#pragma unroll
    for (int o = 0; o < CO; o++) {
#pragma unroll
        for (int s = 16; s > 0; s >>= 1) {
            fsum[o] += __shfl_xor_sync(0xffffffffu, fsum[o], s);
            fsq[o]  += __shfl_xor_sync(0xffffffffu, fsq[o],  s);
        }
    }
    int w = t >> 5, lane = t & 31;
    if (lane == 0) {
#pragma unroll
        for (int o = 0; o < CO; o++) { sRed[w][o] = fsum[o]; sRed[w][CO + o] = fsq[o]; }
    }
    __syncthreads();
    if (t < 2 * CO) {
        float v = 0.f;
#pragma unroll
        for (int b = 0; b < 8; b++) v += sRed[b][t];
        int slice = blockIdx.x & 7;
        if (t < CO) atomicAdd(&g_sumP[slice][t], (double)v);
        else        atomicAdd(&g_sqP[slice][t - CO], (double)v);
    }
}

// ---------------------------------------------------------------------------
// Output: BN4 + leaky + dot with W5[8] + b5.  float4 x 4 iters.
// ---------------------------------------------------------------------------
__global__ void __launch_bounds__(256, 2) k_out(const float* __restrict__ W5,
                                                const float* __restrict__ b5,
                                                float* __restrict__ out) {
    __shared__ float sS[8], sH[8], sW[8];
    __shared__ float sb;
    int t = threadIdx.x;
    if (t < 8) { sS[t] = g_scaleA[3][t]; sH[t] = g_shiftA[3][t]; sW[t] = W5[t]; }
    if (t == 0) sb = b5[0];
    __syncthreads();
    const int base = blockIdx.x * 4096 + t * 4;
#pragma unroll 1
    for (int it = 0; it < 4; it++) {
        const int p = base + it * 1024;
        float4 a = make_float4(sb, sb, sb, sb);
#pragma unroll
        for (int c = 0; c < 8; c++) {
            float4 z = *(const float4*)&g_z[c * NNSZ + p];
            float sc = sS[c], sh = sH[c], w = sW[c];
            float h;
            h = z.x * sc + sh; h = (h >= 0.f) ? h : 0.01f * h; a.x += w * h;
            h = z.y * sc + sh; h = (h >= 0.f) ? h : 0.01f * h; a.y += w * h;
            h = z.z * sc + sh; h = (h >= 0.f) ? h : 0.01f * h; a.z += w * h;
            h = z.w * sc + sh; h = (h >= 0.f) ? h : 0.01f * h; a.w += w * h;
        }
        *(float4*)&out[p] = a;
    }
}

// ---------------------------------------------------------------------------
// Launch: 10 kernels, graph-capturable, allocation-free, no syncs.
// ---------------------------------------------------------------------------
extern "C" void kernel_launch(void* const* d_in, const int* in_sizes, int n_in,
                              void* d_out, int out_size) {
    (void)in_sizes; (void)n_in; (void)out_size;
    const float* x   = (const float*)d_in[0];
    const float* W1  = (const float*)d_in[1];
    const float* b1  = (const float*)d_in[2];
    const float* g1  = (const float*)d_in[3];
    const float* be1 = (const float*)d_in[4];
    const float* W2  = (const float*)d_in[5];
    const float* b2  = (const float*)d_in[6];
    const float* g2  = (const float*)d_in[7];
    const float* be2 = (const float*)d_in[8];
    const float* W3  = (const float*)d_in[9];
    const float* b3  = (const float*)d_in[10];
    const float* g3  = (const float*)d_in[11];
    const float* be3 = (const float*)d_in[12];
    const float* W4  = (const float*)d_in[13];
    const float* b4  = (const float*)d_in[14];
    const float* g4  = (const float*)d_in[15];
    const float* be4 = (const float*)d_in[16];
    const float* W5  = (const float*)d_in[17];
    const float* b5  = (const float*)d_in[18];
    float* out = (float*)d_out;

    k_zero<<<1, 128>>>();
    k_l1<<<dim3(NSZ / 128, NSZ / 8), 256>>>(x, W1, b1);        // z1 + stats1
    k_fin<<<1, 32>>>(g1, be1, 0, 16);
    k_mid1<<<NNSZ / 512, 256>>>(W2, b2);                       // z2 + stats2 (f32x2)
    k_fin<<<1, 32>>>(g2, be2, 1, 16);
    k_mid<16, 8, 2><<<NNSZ / 2048, 256>>>(W3, b3, 1);          // z3 + stats3
    k_fin<<<1, 32>>>(g3, be3, 2, 8);
    k_mid<8, 8, 2><<<NNSZ / 2048, 256>>>(W4, b4, 2);           // z4 + stats4
    k_fin<<<1, 32>>>(g4, be4, 3, 8);
    k_out<<<NNSZ / 4096, 256>>>(W5, b5, out);
}